// round 1
// baseline (speedup 1.0000x reference)
#include <cuda_runtime.h>
#include <cstdint>

#define DDIM 128
#define KDIM 1024
#define BM 128
#define BN 128
#define NTILES (KDIM / BN)
#define THREADS 256
#define ASTRIDE 132   // padded row stride for As (floats), 132*4=528B = 33*16B aligned

typedef unsigned long long ull;

__device__ float g_musp[DDIM * KDIM];
__device__ float g_ealpha[KDIM];

// ---------------- helpers: packed f32x2 ----------------
__device__ __forceinline__ ull pack2(float lo, float hi) {
    ull r;
    asm("mov.b64 %0, {%1, %2};" : "=l"(r) : "f"(lo), "f"(hi));
    return r;
}
__device__ __forceinline__ void unpack2(ull v, float& lo, float& hi) {
    asm("mov.b64 {%0, %1}, %2;" : "=f"(lo), "=f"(hi) : "l"(v));
}
__device__ __forceinline__ void fma2(ull& d, ull a, ull b) {
    asm("fma.rn.f32x2 %0, %1, %2, %3;" : "=l"(d) : "l"(a), "l"(b), "l"(d));
}

// ---------------- prep: normalize mus columns + exp(-10*alpha) ----------------
__global__ void prep_kernel(const float* __restrict__ mus,
                            const float* __restrict__ alphas) {
    int k = blockIdx.x * blockDim.x + threadIdx.x;
    if (k >= KDIM) return;
    float s = 0.0f;
#pragma unroll
    for (int d = 0; d < DDIM; d++) {
        float v = mus[d * KDIM + k];
        s = fmaf(v, v, s);
    }
    float inv = 1.0f / sqrtf(s);
#pragma unroll
    for (int d = 0; d < DDIM; d++)
        g_musp[d * KDIM + k] = mus[d * KDIM + k] * inv;
    g_ealpha[k] = expf(-10.0f * alphas[k]);
}

// ---------------- main: GEMM + fused softmin epilogue ----------------
// per-element soft term: exp(-5 * acos(clip(ip))^2)
__device__ __forceinline__ float softterm(float ip) {
    const float CLIP = 1.0f - 1e-7f;
    float c = fminf(fmaxf(ip, -CLIP), CLIP);
    float t = acosf(c);
    // exp(-5 t^2) = exp2(t*t * (-5*log2(e)))
    return exp2f(t * t * (-7.2134752044448170f));
}

__global__ __launch_bounds__(THREADS, 1)
void gemm_softmin_kernel(const float* __restrict__ xs,
                         float* __restrict__ out) {
    extern __shared__ char smem_raw[];
    float* As = (float*)smem_raw;                               // [DDIM][ASTRIDE]
    ull*   Bs = (ull*)(smem_raw + DDIM * ASTRIDE * 4);          // [DDIM][BN], duplicated pairs

    const int tid = threadIdx.x;
    const int tx = tid & 15;          // 0..15 -> column group (8 cols each)
    const int ty = tid >> 4;          // 0..15 -> row group (8 rows each)
    const int block_row0 = blockIdx.x * BM;

    // ---- load A tile (xs rows, full D) into smem, transposed to [d][row] ----
    {
        const float4* xs4 = (const float4*)(xs + (size_t)block_row0 * DDIM);
#pragma unroll
        for (int i = 0; i < 16; i++) {
            int idx = tid + i * THREADS;      // 0..4095
            int row = idx >> 5;               // 0..127
            int dq  = idx & 31;               // float4 index along D
            float4 v = xs4[row * 32 + dq];
            int d = dq * 4;
            As[(d + 0) * ASTRIDE + row] = v.x;
            As[(d + 1) * ASTRIDE + row] = v.y;
            As[(d + 2) * ASTRIDE + row] = v.z;
            As[(d + 3) * ASTRIDE + row] = v.w;
        }
    }

    float se[8];
#pragma unroll
    for (int r = 0; r < 8; r++) se[r] = 0.0f;

    for (int nt = 0; nt < NTILES; nt++) {
        __syncthreads();   // previous tile's Bs reads done (and As stores visible on nt=0 via next sync)

        // ---- load B tile (mus_p), duplicated into f32x2 pairs ----
#pragma unroll
        for (int i = 0; i < 16; i++) {
            int idx = tid + i * THREADS;      // 0..4095
            int d  = idx >> 5;                // 0..127
            int kq = idx & 31;                // float4 index along BN
            float4 v = *(const float4*)(&g_musp[d * KDIM + nt * BN + kq * 4]);
            ull* br = Bs + d * BN + kq * 4;
            br[0] = pack2(v.x, v.x);
            br[1] = pack2(v.y, v.y);
            br[2] = pack2(v.z, v.z);
            br[3] = pack2(v.w, v.w);
        }
        __syncthreads();

        // ---- accumulate 8x8 micro-tile (4 row-pairs x 8 cols) ----
        ull acc[4][8];
#pragma unroll
        for (int i = 0; i < 4; i++)
#pragma unroll
            for (int j = 0; j < 8; j++) acc[i][j] = 0ull;

#pragma unroll 16
        for (int d = 0; d < DDIM; d++) {
            const ulonglong2 a01 = *(const ulonglong2*)(&As[d * ASTRIDE + ty * 8]);
            const ulonglong2 a23 = *(const ulonglong2*)(&As[d * ASTRIDE + ty * 8 + 4]);
            ull ap[4] = {a01.x, a01.y, a23.x, a23.y};
            const ulonglong2* bp = (const ulonglong2*)(Bs + d * BN + tx * 8);
            ulonglong2 b01 = bp[0], b23 = bp[1], b45 = bp[2], b67 = bp[3];
            ull bb[8] = {b01.x, b01.y, b23.x, b23.y, b45.x, b45.y, b67.x, b67.y};
#pragma unroll
            for (int i = 0; i < 4; i++)
#pragma unroll
                for (int j = 0; j < 8; j++)
                    fma2(acc[i][j], ap[i], bb[j]);
        }

        // ---- epilogue for this column tile ----
        float ea[8];
#pragma unroll
        for (int j = 0; j < 8; j++)
            ea[j] = g_ealpha[nt * BN + tx * 8 + j];

#pragma unroll
        for (int i = 0; i < 4; i++) {
#pragma unroll
            for (int j = 0; j < 8; j++) {
                float lo, hi;
                unpack2(acc[i][j], lo, hi);
                se[2 * i + 0] = fmaf(softterm(lo), ea[j], se[2 * i + 0]);
                se[2 * i + 1] = fmaf(softterm(hi), ea[j], se[2 * i + 1]);
            }
        }
    }

    // ---- reduce row sums across the 16 column-group lanes ----
#pragma unroll
    for (int r = 0; r < 8; r++) {
        float s = se[r];
#pragma unroll
        for (int off = 1; off < 16; off <<= 1)
            s += __shfl_xor_sync(0xffffffffu, s, off);
        se[r] = s;
    }

    if (tx == 0) {
        size_t base = (size_t)block_row0 + ty * 8;
#pragma unroll
        for (int r = 0; r < 8; r++) {
            float S = se[r];
            // F = 0.1*log(S); out = 0.1*log1p(exp(-10F)) = 0.1*log1p(1/S)
            out[base + r] = 0.1f * log1pf(1.0f / S);
        }
    }
}

// ---------------- launch ----------------
extern "C" void kernel_launch(void* const* d_in, const int* in_sizes, int n_in,
                              void* d_out, int out_size) {
    const float* xs     = (const float*)d_in[0];
    const float* mus    = (const float*)d_in[1];
    const float* alphas = (const float*)d_in[2];
    float* out = (float*)d_out;

    int B = in_sizes[0] / DDIM;   // 65536

    static_assert(DDIM * ASTRIDE * 4 % 16 == 0, "align");
    const int smem_bytes = DDIM * ASTRIDE * 4 + DDIM * BN * 8;  // 67584 + 131072 = 198656

    cudaFuncSetAttribute(gemm_softmin_kernel,
                         cudaFuncAttributeMaxDynamicSharedMemorySize, smem_bytes);

    prep_kernel<<<(KDIM + 255) / 256, 256>>>(mus, alphas);
    gemm_softmin_kernel<<<B / BM, THREADS, smem_bytes>>>(xs, out);
}

// round 2
// speedup vs baseline: 5.0131x; 5.0131x over previous
#include <cuda_runtime.h>
#include <cuda_bf16.h>
#include <cstdint>

#define DDIM   128
#define KPROTO 1024
#define NMB    4096          // 65536/16 row-blocks
typedef unsigned int u32;

// Fragment-layout operand storage (static device arrays; no allocation).
__device__ uint4 g_Ah[NMB * 8 * 32];    // 16 MB: A-hi frags  [mb][ks][lane] = {a0,a1,a2,a3}
__device__ uint4 g_Al[NMB * 8 * 32];    // 16 MB: A-lo frags
__device__ uint4 g_B [128 * 8 * 32];    // 512 KB: B frags [nblock][ks][lane] = {b0h,b1h,b0l,b1l}
__device__ float g_la [KPROTO];         // -10*log2(e)*alpha
__device__ float g_inv[KPROTO];         // 1/||mu_col||

// ---------------- helpers ----------------
__device__ __forceinline__ u32 pack_bf16(float lo, float hi) {
    __nv_bfloat162 t;
    t.x = __float2bfloat16_rn(lo);
    t.y = __float2bfloat16_rn(hi);
    return *reinterpret_cast<u32*>(&t);
}
__device__ __forceinline__ void split2(float v, float& h, float& l) {
    __nv_bfloat16 bh = __float2bfloat16_rn(v);
    h = __bfloat162float(bh);
    l = v - h;
}
__device__ __forceinline__ void mma16816(float& d0, float& d1, float& d2, float& d3,
                                         u32 a0, u32 a1, u32 a2, u32 a3,
                                         u32 b0, u32 b1) {
    asm volatile(
        "mma.sync.aligned.m16n8k16.row.col.f32.bf16.bf16.f32 "
        "{%0,%1,%2,%3},{%4,%5,%6,%7},{%8,%9},{%0,%1,%2,%3};"
        : "+f"(d0), "+f"(d1), "+f"(d2), "+f"(d3)
        : "r"(a0), "r"(a1), "r"(a2), "r"(a3), "r"(b0), "r"(b1));
}

// acos(x) = sqrt(1-x) * poly(x) on [0,1]  (Hastings / A&S 4.4.45, |err|<=2e-8)
__device__ __forceinline__ float term(float ip, float la) {
    float ax = fabsf(ip);
    float t  = fmaxf(1.0f - ax, 0.0f);
    float sq; asm("sqrt.approx.f32 %0, %1;" : "=f"(sq) : "f"(t));
    float p  =            -0.0012624911f;
    p = fmaf(p, ax,        0.0066700901f);
    p = fmaf(p, ax,       -0.0170881256f);
    p = fmaf(p, ax,        0.0308918810f);
    p = fmaf(p, ax,       -0.0501743046f);
    p = fmaf(p, ax,        0.0889789874f);
    p = fmaf(p, ax,       -0.2145988016f);
    p = fmaf(p, ax,        1.5707963050f);
    float th = sq * p;
    th = (ip >= 0.0f) ? th : (3.14159265358979f - th);
    float z = fmaf(th * th, -7.213475204444817f, la);   // -5*log2e*theta^2 + la
    float e; asm("ex2.approx.f32 %0, %1;" : "=f"(e) : "f"(z));
    return e;
}

// ---------------- prep 1: column norms + log2-alpha ----------------
__global__ void prep1(const float* __restrict__ mus, const float* __restrict__ alphas) {
    int n = blockIdx.x * blockDim.x + threadIdx.x;
    if (n >= KPROTO) return;
    float s = 0.0f;
#pragma unroll 8
    for (int d = 0; d < DDIM; d++) {
        float v = mus[d * KPROTO + n];
        s = fmaf(v, v, s);
    }
    g_inv[n] = rsqrtf(s);
    g_la[n]  = -14.426950408889634f * alphas[n];   // -10*log2(e)*alpha
}

// ---------------- prep 2: B fragments ----------------
__global__ void prep2(const float* __restrict__ mus) {
    int gid  = blockIdx.x * blockDim.x + threadIdx.x;   // 32768 threads
    int lane = gid & 31;
    int f    = gid >> 5;            // 0..1023 = nblock*8 + ks
    int nblk = f >> 3;
    int ks   = f & 7;
    int g    = lane >> 2;
    int t4   = lane & 3;
    int n    = nblk * 8 + g;
    int k0   = ks * 16 + 2 * t4;
    float inv = g_inv[n];
    float v0 = mus[(k0 + 0) * KPROTO + n] * inv;
    float v1 = mus[(k0 + 1) * KPROTO + n] * inv;
    float v2 = mus[(k0 + 8) * KPROTO + n] * inv;
    float v3 = mus[(k0 + 9) * KPROTO + n] * inv;
    float h0, l0, h1, l1, h2, l2, h3, l3;
    split2(v0, h0, l0); split2(v1, h1, l1);
    split2(v2, h2, l2); split2(v3, h3, l3);
    uint4 o;
    o.x = pack_bf16(h0, h1);  // b0 hi
    o.y = pack_bf16(h2, h3);  // b1 hi
    o.z = pack_bf16(l0, l1);  // b0 lo
    o.w = pack_bf16(l2, l3);  // b1 lo
    g_B[f * 32 + lane] = o;
}

// ---------------- prep 3: A fragments ----------------
__global__ void prepA(const float* __restrict__ xs) {
    int tid  = threadIdx.x;
    int w    = tid >> 5;            // = ks
    int lane = tid & 31;
    int mb   = blockIdx.x;          // 0..4095
    int g    = lane >> 2;
    int t4   = lane & 3;
    int ks   = w;
    int r0 = mb * 16 + g;
    int r1 = r0 + 8;
    int c0 = ks * 16 + 2 * t4;
    float2 p00 = *(const float2*)&xs[(size_t)r0 * DDIM + c0];
    float2 p01 = *(const float2*)&xs[(size_t)r0 * DDIM + c0 + 8];
    float2 p10 = *(const float2*)&xs[(size_t)r1 * DDIM + c0];
    float2 p11 = *(const float2*)&xs[(size_t)r1 * DDIM + c0 + 8];
    float h, l;
    uint4 oh, ol;
    float h2, l2;
    split2(p00.x, h, l);  split2(p00.y, h2, l2);
    oh.x = pack_bf16(h, h2);  ol.x = pack_bf16(l, l2);
    split2(p10.x, h, l);  split2(p10.y, h2, l2);
    oh.y = pack_bf16(h, h2);  ol.y = pack_bf16(l, l2);
    split2(p01.x, h, l);  split2(p01.y, h2, l2);
    oh.z = pack_bf16(h, h2);  ol.z = pack_bf16(l, l2);
    split2(p11.x, h, l);  split2(p11.y, h2, l2);
    oh.w = pack_bf16(h, h2);  ol.w = pack_bf16(l, l2);
    size_t idx = ((size_t)mb * 8 + ks) * 32 + lane;
    g_Ah[idx] = oh;
    g_Al[idx] = ol;
}

// ---------------- main: mma + fused softmin epilogue ----------------
__global__ __launch_bounds__(256, 1)
void main_kernel(float* __restrict__ out) {
    int tid  = threadIdx.x;
    int w    = tid >> 5;
    int lane = tid & 31;
    int g    = lane >> 2;
    int t4   = lane & 3;
    int mb   = blockIdx.x * 8 + w;

    // A fragments: register-resident for the whole kernel (hi+lo, 8 ksteps)
    uint4 Ah[8], Al[8];
    {
        const uint4* pA  = g_Ah + (size_t)mb * 8 * 32 + lane;
        const uint4* pAl = g_Al + (size_t)mb * 8 * 32 + lane;
#pragma unroll
        for (int ks = 0; ks < 8; ks++) { Ah[ks] = pA[ks * 32]; Al[ks] = pAl[ks * 32]; }
    }

    float s0 = 0.0f, s1 = 0.0f;
    const float2* la_p = (const float2*)g_la;

    for (int nbo = 0; nbo < 128; nbo += 16) {
        __syncthreads();   // keep warps converged so B frags hit in L1 across warps
#pragma unroll 2
        for (int nbi = 0; nbi < 16; nbi++) {
            int nb = nbo + nbi;
            const uint4* pB = g_B + nb * 8 * 32 + lane;
            float2 la = la_p[nb * 4 + t4];

            float hh0 = 0, hh1 = 0, hh2 = 0, hh3 = 0;
            float hl0 = 0, hl1 = 0, hl2 = 0, hl3 = 0;
            float lh0 = 0, lh1 = 0, lh2 = 0, lh3 = 0;
#pragma unroll
            for (int ks = 0; ks < 8; ks++) {
                uint4 b = pB[ks * 32];
                mma16816(hh0, hh1, hh2, hh3, Ah[ks].x, Ah[ks].y, Ah[ks].z, Ah[ks].w, b.x, b.y);
                mma16816(hl0, hl1, hl2, hl3, Ah[ks].x, Ah[ks].y, Ah[ks].z, Ah[ks].w, b.z, b.w);
                mma16816(lh0, lh1, lh2, lh3, Al[ks].x, Al[ks].y, Al[ks].z, Al[ks].w, b.x, b.y);
            }
            float ip0 = hh0 + (hl0 + lh0);   // (row g,   col 2t4)
            float ip1 = hh1 + (hl1 + lh1);   // (row g,   col 2t4+1)
            float ip2 = hh2 + (hl2 + lh2);   // (row g+8, col 2t4)
            float ip3 = hh3 + (hl3 + lh3);   // (row g+8, col 2t4+1)
            s0 += term(ip0, la.x) + term(ip1, la.y);
            s1 += term(ip2, la.x) + term(ip3, la.y);
        }
    }

    // reduce across the 4 lanes sharing the same rows (t4 = 0..3)
    s0 += __shfl_xor_sync(0xffffffffu, s0, 1);
    s0 += __shfl_xor_sync(0xffffffffu, s0, 2);
    s1 += __shfl_xor_sync(0xffffffffu, s1, 1);
    s1 += __shfl_xor_sync(0xffffffffu, s1, 2);

    if (t4 == 0) {
        int r = mb * 16 + g;
        out[r]     = 0.1f * log1pf(1.0f / s0);
        out[r + 8] = 0.1f * log1pf(1.0f / s1);
    }
}

// ---------------- launch ----------------
extern "C" void kernel_launch(void* const* d_in, const int* in_sizes, int n_in,
                              void* d_out, int out_size) {
    const float* xs     = (const float*)d_in[0];
    const float* mus    = (const float*)d_in[1];
    const float* alphas = (const float*)d_in[2];
    float* out = (float*)d_out;

    int B = in_sizes[0] / DDIM;    // 65536

    prep1<<<(KPROTO + 255) / 256, 256>>>(mus, alphas);
    prep2<<<128, 256>>>(mus);
    prepA<<<B / 16, 256>>>(xs);
    main_kernel<<<B / 128, 256>>>(out);
}

// round 4
// speedup vs baseline: 6.3621x; 1.2691x over previous
#include <cuda_runtime.h>
#include <cuda_bf16.h>
#include <cstdint>

#define DDIM   128
#define KPROTO 1024
#define NMB    4096          // 65536/16 row-strips
#define THREADS 512
typedef unsigned int u32;
typedef unsigned long long ull;

// Fragment-layout operand storage (static device arrays; no allocation).
__device__ uint4 g_Ah[NMB * 8 * 32];    // 16 MB: A-hi frags  [mb][ks][lane]
__device__ uint4 g_Al[NMB * 8 * 32];    // 16 MB: A-lo frags
__device__ uint4 g_B [128 * 8 * 32];    // 512 KB: B frags [nblock][ks][lane] = {b0h,b1h,b0l,b1l}
__device__ float g_la [KPROTO];         // -10*log2(e)*alpha
__device__ float g_inv[KPROTO];         // 1/||mu_col||

// ---------------- helpers ----------------
__device__ __forceinline__ u32 pack_bf16(float lo, float hi) {
    __nv_bfloat162 t;
    t.x = __float2bfloat16_rn(lo);
    t.y = __float2bfloat16_rn(hi);
    return *reinterpret_cast<u32*>(&t);
}
__device__ __forceinline__ void split2(float v, float& h, float& l) {
    __nv_bfloat16 bh = __float2bfloat16_rn(v);
    h = __bfloat162float(bh);
    l = v - h;
}
__device__ __forceinline__ void mma16816(float& d0, float& d1, float& d2, float& d3,
                                         u32 a0, u32 a1, u32 a2, u32 a3,
                                         u32 b0, u32 b1) {
    asm volatile(
        "mma.sync.aligned.m16n8k16.row.col.f32.bf16.bf16.f32 "
        "{%0,%1,%2,%3},{%4,%5,%6,%7},{%8,%9},{%0,%1,%2,%3};"
        : "+f"(d0), "+f"(d1), "+f"(d2), "+f"(d3)
        : "r"(a0), "r"(a1), "r"(a2), "r"(a3), "r"(b0), "r"(b1));
}

// acos(x) = sqrt(1-x) * poly(x) on [0,1]  (A&S 4.4.45, |err|<=2e-8)
__device__ __forceinline__ float term(float ip, float la) {
    float ax = fabsf(ip);
    float t  = fmaxf(1.0f - ax, 0.0f);
    float sq; asm("sqrt.approx.f32 %0, %1;" : "=f"(sq) : "f"(t));
    float p  =            -0.0012624911f;
    p = fmaf(p, ax,        0.0066700901f);
    p = fmaf(p, ax,       -0.0170881256f);
    p = fmaf(p, ax,        0.0308918810f);
    p = fmaf(p, ax,       -0.0501743046f);
    p = fmaf(p, ax,        0.0889789874f);
    p = fmaf(p, ax,       -0.2145988016f);
    p = fmaf(p, ax,        1.5707963050f);
    float th = sq * p;
    th = (ip >= 0.0f) ? th : (3.14159265358979f - th);
    float z = fmaf(th * th, -7.213475204444817f, la);   // -5*log2e*theta^2 + la
    float e; asm("ex2.approx.f32 %0, %1;" : "=f"(e) : "f"(z));
    return e;
}

// ---------------- prep 1: column norms + log2-alpha ----------------
__global__ void prep1(const float* __restrict__ mus, const float* __restrict__ alphas) {
    int n = blockIdx.x * blockDim.x + threadIdx.x;
    if (n >= KPROTO) return;
    float s = 0.0f;
#pragma unroll 8
    for (int d = 0; d < DDIM; d++) {
        float v = mus[d * KPROTO + n];
        s = fmaf(v, v, s);
    }
    g_inv[n] = rsqrtf(s);
    g_la[n]  = -14.426950408889634f * alphas[n];   // -10*log2(e)*alpha
}

// ---------------- prep 2: B fragments ----------------
__global__ void prep2(const float* __restrict__ mus) {
    int gid  = blockIdx.x * blockDim.x + threadIdx.x;   // 32768 threads
    int lane = gid & 31;
    int f    = gid >> 5;            // 0..1023 = nblock*8 + ks
    int nblk = f >> 3;
    int ks   = f & 7;
    int g    = lane >> 2;
    int t4   = lane & 3;
    int n    = nblk * 8 + g;
    int k0   = ks * 16 + 2 * t4;
    float inv = g_inv[n];
    float v0 = mus[(k0 + 0) * KPROTO + n] * inv;
    float v1 = mus[(k0 + 1) * KPROTO + n] * inv;
    float v2 = mus[(k0 + 8) * KPROTO + n] * inv;
    float v3 = mus[(k0 + 9) * KPROTO + n] * inv;
    float h0, l0, h1, l1, h2, l2, h3, l3;
    split2(v0, h0, l0); split2(v1, h1, l1);
    split2(v2, h2, l2); split2(v3, h3, l3);
    uint4 o;
    o.x = pack_bf16(h0, h1);
    o.y = pack_bf16(h2, h3);
    o.z = pack_bf16(l0, l1);
    o.w = pack_bf16(l2, l3);
    g_B[f * 32 + lane] = o;
}

// ---------------- prep 3: A fragments ----------------
__global__ void prepA(const float* __restrict__ xs) {
    int tid  = threadIdx.x;
    int w    = tid >> 5;            // = ks
    int lane = tid & 31;
    int mb   = blockIdx.x;          // 0..4095
    int g    = lane >> 2;
    int t4   = lane & 3;
    int ks   = w;
    int r0 = mb * 16 + g;
    int r1 = r0 + 8;
    int c0 = ks * 16 + 2 * t4;
    float2 p00 = *(const float2*)&xs[(size_t)r0 * DDIM + c0];
    float2 p01 = *(const float2*)&xs[(size_t)r0 * DDIM + c0 + 8];
    float2 p10 = *(const float2*)&xs[(size_t)r1 * DDIM + c0];
    float2 p11 = *(const float2*)&xs[(size_t)r1 * DDIM + c0 + 8];
    float h, l, h2, l2;
    uint4 oh, ol;
    split2(p00.x, h, l);  split2(p00.y, h2, l2);
    oh.x = pack_bf16(h, h2);  ol.x = pack_bf16(l, l2);
    split2(p10.x, h, l);  split2(p10.y, h2, l2);
    oh.y = pack_bf16(h, h2);  ol.y = pack_bf16(l, l2);
    split2(p01.x, h, l);  split2(p01.y, h2, l2);
    oh.z = pack_bf16(h, h2);  ol.z = pack_bf16(l, l2);
    split2(p11.x, h, l);  split2(p11.y, h2, l2);
    oh.w = pack_bf16(h, h2);  ol.w = pack_bf16(l, l2);
    size_t idx = ((size_t)mb * 8 + ks) * 32 + lane;
    g_Ah[idx] = oh;
    g_Al[idx] = ol;
}

// ---------------- main: mma + fused softmin epilogue ----------------
// Block = 512 threads = 16 warps = 8 strips x 2 warps; block covers 128 rows.
// Warp pair (strip s): warp half=0 does proto-blocks 0..63, half=1 does 64..127.
__global__ __launch_bounds__(THREADS, 1)
void main_kernel(float* __restrict__ out) {
    __shared__ uint4 sAl[8 * 8 * 32];      // 32 KB: A-lo frags [strip][ks][lane]
    __shared__ float red[2][128];          // warp-pair partial sums

    const int tid   = threadIdx.x;
    const int wid   = tid >> 5;
    const int lane  = tid & 31;
    const int strip = wid >> 1;            // 0..7
    const int half  = wid & 1;             // column half
    const int g     = lane >> 2;
    const int t4    = lane & 3;
    const int mb    = blockIdx.x * 8 + strip;

    // stage this block's A-lo fragments into smem (linear copy; layouts match)
    {
        const uint4* src = g_Al + (size_t)blockIdx.x * 2048;
#pragma unroll
        for (int i = tid; i < 2048; i += THREADS) sAl[i] = src[i];
    }

    // A-hi fragments: register-resident (8 ksteps x 4 regs)
    uint4 Ah[8];
    {
        const uint4* pA = g_Ah + (size_t)mb * 8 * 32 + lane;
#pragma unroll
        for (int ks = 0; ks < 8; ks++) Ah[ks] = pA[ks * 32];
    }
    __syncthreads();

    const uint4* myAl = sAl + strip * 256 + lane;
    float s0 = 0.0f, s1 = 0.0f;
    const float2* la_p = (const float2*)g_la;

    const int nb0 = half * 64;
#pragma unroll 1
    for (int nbi = 0; nbi < 64; nbi++) {
        int nb = nb0 + nbi;
        const uint4* pB = g_B + nb * 8 * 32 + lane;
        float2 la = la_p[nb * 4 + t4];

        float hh0 = 0, hh1 = 0, hh2 = 0, hh3 = 0;
        float hl0 = 0, hl1 = 0, hl2 = 0, hl3 = 0;
        float lh0 = 0, lh1 = 0, lh2 = 0, lh3 = 0;
#pragma unroll
        for (int ks = 0; ks < 8; ks++) {
            uint4 b  = pB[ks * 32];
            uint4 al = myAl[ks * 32];
            mma16816(hh0, hh1, hh2, hh3, Ah[ks].x, Ah[ks].y, Ah[ks].z, Ah[ks].w, b.x, b.y);
            mma16816(hl0, hl1, hl2, hl3, Ah[ks].x, Ah[ks].y, Ah[ks].z, Ah[ks].w, b.z, b.w);
            mma16816(lh0, lh1, lh2, lh3, al.x, al.y, al.z, al.w, b.x, b.y);
        }
        float ip0 = hh0 + (hl0 + lh0);
        float ip1 = hh1 + (hl1 + lh1);
        float ip2 = hh2 + (hl2 + lh2);
        float ip3 = hh3 + (hl3 + lh3);
        s0 += term(ip0, la.x) + term(ip1, la.y);
        s1 += term(ip2, la.x) + term(ip3, la.y);
    }

    // intra-warp reduce across the 4 lanes sharing the same rows
    s0 += __shfl_xor_sync(0xffffffffu, s0, 1);
    s0 += __shfl_xor_sync(0xffffffffu, s0, 2);
    s1 += __shfl_xor_sync(0xffffffffu, s1, 1);
    s1 += __shfl_xor_sync(0xffffffffu, s1, 2);

    if (t4 == 0) {
        red[half][strip * 16 + g]     = s0;
        red[half][strip * 16 + g + 8] = s1;
    }
    __syncthreads();

    if (tid < 128) {
        float S = red[0][tid] + red[1][tid];
        out[blockIdx.x * 128 + tid] = 0.1f * log1pf(1.0f / S);
    }
}

// ---------------- launch ----------------
extern "C" void kernel_launch(void* const* d_in, const int* in_sizes, int n_in,
                              void* d_out, int out_size) {
    const float* xs     = (const float*)d_in[0];
    const float* mus    = (const float*)d_in[1];
    const float* alphas = (const float*)d_in[2];
    float* out = (float*)d_out;

    int B = in_sizes[0] / DDIM;    // 65536

    prep1<<<(KPROTO + 255) / 256, 256>>>(mus, alphas);
    prep2<<<128, 256>>>(mus);
    prepA<<<B / 16, 256>>>(xs);
    main_kernel<<<B / 128, THREADS>>>(out);
}

// round 5
// speedup vs baseline: 6.7339x; 1.0584x over previous
#include <cuda_runtime.h>
#include <cuda_bf16.h>
#include <cstdint>

#define DDIM   128
#define KPROTO 1024
#define NMB    4096          // 65536/16 row-strips
#define THREADS 256
typedef unsigned int u32;

// Fragment-layout operand storage (static device arrays; no allocation).
__device__ uint4 g_Ah[NMB * 8 * 32];    // 16 MB: A-hi frags  [mb][ks][lane]
__device__ uint4 g_Al[NMB * 8 * 32];    // 16 MB: A-lo frags
__device__ uint4 g_B [128 * 8 * 32];    // 512 KB: B frags [nblock][ks][lane] = {b0h,b1h,b0l,b1l}
__device__ float g_la [KPROTO];         // -10*log2(e)*alpha
__device__ float g_inv[KPROTO];         // 1/||mu_col||

// ---------------- helpers ----------------
__device__ __forceinline__ u32 pack_bf16(float lo, float hi) {
    __nv_bfloat162 t;
    t.x = __float2bfloat16_rn(lo);
    t.y = __float2bfloat16_rn(hi);
    return *reinterpret_cast<u32*>(&t);
}
__device__ __forceinline__ void split2(float v, float& h, float& l) {
    __nv_bfloat16 bh = __float2bfloat16_rn(v);
    h = __bfloat162float(bh);
    l = v - h;
}
__device__ __forceinline__ void mma16816(float& d0, float& d1, float& d2, float& d3,
                                         u32 a0, u32 a1, u32 a2, u32 a3,
                                         u32 b0, u32 b1) {
    asm volatile(
        "mma.sync.aligned.m16n8k16.row.col.f32.bf16.bf16.f32 "
        "{%0,%1,%2,%3},{%4,%5,%6,%7},{%8,%9},{%0,%1,%2,%3};"
        : "+f"(d0), "+f"(d1), "+f"(d2), "+f"(d3)
        : "r"(a0), "r"(a1), "r"(a2), "r"(a3), "r"(b0), "r"(b1));
}

// acos(x) = sqrt(1-x) * poly(x) on [0,1]  (A&S 4.4.45, |err|<=2e-8)
__device__ __forceinline__ float term(float ip, float la) {
    float ax = fabsf(ip);
    float t  = fmaxf(1.0f - ax, 0.0f);
    float sq; asm("sqrt.approx.f32 %0, %1;" : "=f"(sq) : "f"(t));
    float p  =            -0.0012624911f;
    p = fmaf(p, ax,        0.0066700901f);
    p = fmaf(p, ax,       -0.0170881256f);
    p = fmaf(p, ax,        0.0308918810f);
    p = fmaf(p, ax,       -0.0501743046f);
    p = fmaf(p, ax,        0.0889789874f);
    p = fmaf(p, ax,       -0.2145988016f);
    p = fmaf(p, ax,        1.5707963050f);
    float th = sq * p;
    th = (ip >= 0.0f) ? th : (3.14159265358979f - th);
    float z = fmaf(th * th, -7.213475204444817f, la);   // -5*log2e*theta^2 + la
    float e; asm("ex2.approx.f32 %0, %1;" : "=f"(e) : "f"(z));
    return e;
}

// ---------------- prep 1: column norms + log2-alpha ----------------
__global__ void prep1(const float* __restrict__ mus, const float* __restrict__ alphas) {
    int n = blockIdx.x * blockDim.x + threadIdx.x;
    if (n >= KPROTO) return;
    float s = 0.0f;
#pragma unroll 8
    for (int d = 0; d < DDIM; d++) {
        float v = mus[d * KPROTO + n];
        s = fmaf(v, v, s);
    }
    g_inv[n] = rsqrtf(s);
    g_la[n]  = -14.426950408889634f * alphas[n];   // -10*log2(e)*alpha
}

// ---------------- prep 2: B fragments ----------------
__global__ void prep2(const float* __restrict__ mus) {
    int gid  = blockIdx.x * blockDim.x + threadIdx.x;   // 32768 threads
    int lane = gid & 31;
    int f    = gid >> 5;            // 0..1023 = nblock*8 + ks
    int nblk = f >> 3;
    int ks   = f & 7;
    int g    = lane >> 2;
    int t4   = lane & 3;
    int n    = nblk * 8 + g;
    int k0   = ks * 16 + 2 * t4;
    float inv = g_inv[n];
    float v0 = mus[(k0 + 0) * KPROTO + n] * inv;
    float v1 = mus[(k0 + 1) * KPROTO + n] * inv;
    float v2 = mus[(k0 + 8) * KPROTO + n] * inv;
    float v3 = mus[(k0 + 9) * KPROTO + n] * inv;
    float h0, l0, h1, l1, h2, l2, h3, l3;
    split2(v0, h0, l0); split2(v1, h1, l1);
    split2(v2, h2, l2); split2(v3, h3, l3);
    uint4 o;
    o.x = pack_bf16(h0, h1);
    o.y = pack_bf16(h2, h3);
    o.z = pack_bf16(l0, l1);
    o.w = pack_bf16(l2, l3);
    g_B[f * 32 + lane] = o;
}

// ---------------- prep 3: A fragments ----------------
__global__ void prepA(const float* __restrict__ xs) {
    int tid  = threadIdx.x;
    int w    = tid >> 5;            // = ks
    int lane = tid & 31;
    int mb   = blockIdx.x;          // 0..4095
    int g    = lane >> 2;
    int t4   = lane & 3;
    int ks   = w;
    int r0 = mb * 16 + g;
    int r1 = r0 + 8;
    int c0 = ks * 16 + 2 * t4;
    float2 p00 = *(const float2*)&xs[(size_t)r0 * DDIM + c0];
    float2 p01 = *(const float2*)&xs[(size_t)r0 * DDIM + c0 + 8];
    float2 p10 = *(const float2*)&xs[(size_t)r1 * DDIM + c0];
    float2 p11 = *(const float2*)&xs[(size_t)r1 * DDIM + c0 + 8];
    float h, l, h2, l2;
    uint4 oh, ol;
    split2(p00.x, h, l);  split2(p00.y, h2, l2);
    oh.x = pack_bf16(h, h2);  ol.x = pack_bf16(l, l2);
    split2(p10.x, h, l);  split2(p10.y, h2, l2);
    oh.y = pack_bf16(h, h2);  ol.y = pack_bf16(l, l2);
    split2(p01.x, h, l);  split2(p01.y, h2, l2);
    oh.z = pack_bf16(h, h2);  ol.z = pack_bf16(l, l2);
    split2(p11.x, h, l);  split2(p11.y, h2, l2);
    oh.w = pack_bf16(h, h2);  ol.w = pack_bf16(l, l2);
    size_t idx = ((size_t)mb * 8 + ks) * 32 + lane;
    g_Ah[idx] = oh;
    g_Al[idx] = ol;
}

// ---------------- main: mma + fused softmin epilogue ----------------
// Block = 256 threads = 8 warps = 8 strips of 16 rows (128 rows/block).
// Every warp sweeps ALL 128 proto-blocks in the same order (coherent B stream,
// L1 temporal reuse across the 8 warps). A-hi AND A-lo register-resident:
// zero shared memory, zero LDS — only 8 LDG.128 per iteration.
__global__ __launch_bounds__(THREADS, 2)
void main_kernel(float* __restrict__ out) {
    const int tid  = threadIdx.x;
    const int wid  = tid >> 5;
    const int lane = tid & 31;
    const int g    = lane >> 2;
    const int t4   = lane & 3;
    const int mb   = blockIdx.x * 8 + wid;

    // A fragments: register-resident for the whole kernel (hi+lo, 8 ksteps)
    uint4 Ah[8], Al[8];
    {
        const uint4* pA  = g_Ah + (size_t)mb * 256 + lane;
        const uint4* pAl = g_Al + (size_t)mb * 256 + lane;
#pragma unroll
        for (int ks = 0; ks < 8; ks++) { Ah[ks] = pA[ks * 32]; Al[ks] = pAl[ks * 32]; }
    }

    float s0 = 0.0f, s1 = 0.0f;
    const float2* la_p = (const float2*)g_la;

#pragma unroll 1
    for (int nb = 0; nb < 128; nb++) {
        const uint4* pB = g_B + nb * 256 + lane;
        float2 la = la_p[nb * 4 + t4];

        float hh0 = 0, hh1 = 0, hh2 = 0, hh3 = 0;
        float hl0 = 0, hl1 = 0, hl2 = 0, hl3 = 0;
        float lh0 = 0, lh1 = 0, lh2 = 0, lh3 = 0;
#pragma unroll
        for (int ks = 0; ks < 8; ks++) {
            uint4 b = pB[ks * 32];
            mma16816(hh0, hh1, hh2, hh3, Ah[ks].x, Ah[ks].y, Ah[ks].z, Ah[ks].w, b.x, b.y);
            mma16816(hl0, hl1, hl2, hl3, Ah[ks].x, Ah[ks].y, Ah[ks].z, Ah[ks].w, b.z, b.w);
            mma16816(lh0, lh1, lh2, lh3, Al[ks].x, Al[ks].y, Al[ks].z, Al[ks].w, b.x, b.y);
        }
        float ip0 = hh0 + (hl0 + lh0);   // (row g,   col 2t4)
        float ip1 = hh1 + (hl1 + lh1);   // (row g,   col 2t4+1)
        float ip2 = hh2 + (hl2 + lh2);   // (row g+8, col 2t4)
        float ip3 = hh3 + (hl3 + lh3);   // (row g+8, col 2t4+1)
        s0 += term(ip0, la.x) + term(ip1, la.y);
        s1 += term(ip2, la.x) + term(ip3, la.y);
    }

    // reduce across the 4 lanes sharing the same rows (t4 = 0..3)
    s0 += __shfl_xor_sync(0xffffffffu, s0, 1);
    s0 += __shfl_xor_sync(0xffffffffu, s0, 2);
    s1 += __shfl_xor_sync(0xffffffffu, s1, 1);
    s1 += __shfl_xor_sync(0xffffffffu, s1, 2);

    if (t4 == 0) {
        int r = mb * 16 + g;
        out[r]     = 0.1f * log1pf(1.0f / s0);
        out[r + 8] = 0.1f * log1pf(1.0f / s1);
    }
}

// ---------------- launch ----------------
extern "C" void kernel_launch(void* const* d_in, const int* in_sizes, int n_in,
                              void* d_out, int out_size) {
    const float* xs     = (const float*)d_in[0];
    const float* mus    = (const float*)d_in[1];
    const float* alphas = (const float*)d_in[2];
    float* out = (float*)d_out;

    int B = in_sizes[0] / DDIM;    // 65536

    prep1<<<(KPROTO + 255) / 256, 256>>>(mus, alphas);
    prep2<<<128, 256>>>(mus);
    prepA<<<B / 16, 256>>>(xs);
    main_kernel<<<B / 128, THREADS>>>(out);
}

// round 6
// speedup vs baseline: 7.3788x; 1.0958x over previous
#include <cuda_runtime.h>
#include <cuda_fp16.h>
#include <cstdint>

#define DDIM   128
#define KPROTO 1024
#define NMB    4096          // 65536/16 row-strips
#define THREADS 64
typedef unsigned int u32;
typedef unsigned long long ull;

// Fragment-layout operand storage (static device arrays; no allocation).
__device__ uint4 g_Ah[NMB * 8 * 32];    // 8 MB eff: A fp16 frags [mb][ks][lane] = {a0,a1,a2,a3}
__device__ uint4 g_B [128 * 8 * 32];    // 512 KB: B frags [nblock][ks][lane] = {b0h,b1h,b0l,b1l}
__device__ float g_la [KPROTO];         // -10*log2(e)*alpha
__device__ float g_inv[KPROTO];         // 1/||mu_col||

// ---------------- helpers ----------------
__device__ __forceinline__ u32 pack_h2(float a, float b) {
    __half2 t;
    t.x = __float2half_rn(a);
    t.y = __float2half_rn(b);
    return *reinterpret_cast<u32*>(&t);
}
__device__ __forceinline__ void splith(float v, float& h, float& l) {
    __half hh = __float2half_rn(v);
    h = __half2float(hh);
    l = v - h;
}
__device__ __forceinline__ ull pack2(float lo, float hi) {
    ull r; asm("mov.b64 %0, {%1, %2};" : "=l"(r) : "f"(lo), "f"(hi)); return r;
}
__device__ __forceinline__ void unpack2(ull v, float& lo, float& hi) {
    asm("mov.b64 {%0, %1}, %2;" : "=f"(lo), "=f"(hi) : "l"(v));
}
__device__ __forceinline__ ull fma2(ull a, ull b, ull c) {
    ull d; asm("fma.rn.f32x2 %0, %1, %2, %3;" : "=l"(d) : "l"(a), "l"(b), "l"(c)); return d;
}
__device__ __forceinline__ ull mul2(ull a, ull b) {
    ull d; asm("mul.rn.f32x2 %0, %1, %2;" : "=l"(d) : "l"(a), "l"(b)); return d;
}
__device__ __forceinline__ float ex2(float x) {
    float r; asm("ex2.approx.f32 %0, %1;" : "=f"(r) : "f"(x)); return r;
}
__device__ __forceinline__ float sqap(float x) {
    float r; asm("sqrt.approx.f32 %0, %1;" : "=f"(r) : "f"(x)); return r;
}
__device__ __forceinline__ void mma16816h(float& d0, float& d1, float& d2, float& d3,
                                          u32 a0, u32 a1, u32 a2, u32 a3,
                                          u32 b0, u32 b1) {
    asm volatile(
        "mma.sync.aligned.m16n8k16.row.col.f32.f16.f16.f32 "
        "{%0,%1,%2,%3},{%4,%5,%6,%7},{%8,%9},{%0,%1,%2,%3};"
        : "+f"(d0), "+f"(d1), "+f"(d2), "+f"(d3)
        : "r"(a0), "r"(a1), "r"(a2), "r"(a3), "r"(b0), "r"(b1));
}

// packed epilogue: e_i = exp2(-5*log2e*acos(ip_i)^2 + la_i) for a pair
__device__ __forceinline__ void term2(float ip0, float ip1, ull la2, float& e0, float& e1) {
    const float PI = 3.14159265358979f;
    float ax0 = fabsf(ip0), ax1 = fabsf(ip1);
    float sq0 = sqap(fmaxf(1.0f - ax0, 0.0f));
    float sq1 = sqap(fmaxf(1.0f - ax1, 0.0f));
    ull ax2 = pack2(ax0, ax1);
    // A&S 4.4.45 deg-7 Horner, packed
    ull P = pack2(-0.0012624911f, -0.0012624911f);
    P = fma2(P, ax2, pack2( 0.0066700901f,  0.0066700901f));
    P = fma2(P, ax2, pack2(-0.0170881256f, -0.0170881256f));
    P = fma2(P, ax2, pack2( 0.0308918810f,  0.0308918810f));
    P = fma2(P, ax2, pack2(-0.0501743046f, -0.0501743046f));
    P = fma2(P, ax2, pack2( 0.0889789874f,  0.0889789874f));
    P = fma2(P, ax2, pack2(-0.2145988016f, -0.2145988016f));
    P = fma2(P, ax2, pack2( 1.5707963050f,  1.5707963050f));
    float p0, p1; unpack2(P, p0, p1);
    float th0 = sq0 * p0;  th0 = (ip0 >= 0.0f) ? th0 : PI - th0;
    float th1 = sq1 * p1;  th1 = (ip1 >= 0.0f) ? th1 : PI - th1;
    ull th2 = pack2(th0, th1);
    ull z2  = fma2(mul2(th2, th2), pack2(-7.213475204444817f, -7.213475204444817f), la2);
    float z0, z1; unpack2(z2, z0, z1);
    e0 = ex2(z0);
    e1 = ex2(z1);
}

// ---------------- prep 1: column norms + log2-alpha ----------------
__global__ void prep1(const float* __restrict__ mus, const float* __restrict__ alphas) {
    int n = blockIdx.x * blockDim.x + threadIdx.x;
    if (n >= KPROTO) return;
    float s = 0.0f;
#pragma unroll 8
    for (int d = 0; d < DDIM; d++) {
        float v = mus[d * KPROTO + n];
        s = fmaf(v, v, s);
    }
    g_inv[n] = rsqrtf(s);
    g_la[n]  = -14.426950408889634f * alphas[n];   // -10*log2(e)*alpha
}

// ---------------- prep 2: B fragments (fp16 hi/lo) ----------------
__global__ void prep2(const float* __restrict__ mus) {
    int gid  = blockIdx.x * blockDim.x + threadIdx.x;   // 32768 threads
    int lane = gid & 31;
    int f    = gid >> 5;            // 0..1023 = nblock*8 + ks
    int nblk = f >> 3;
    int ks   = f & 7;
    int g    = lane >> 2;
    int t4   = lane & 3;
    int n    = nblk * 8 + g;
    int k0   = ks * 16 + 2 * t4;
    float inv = g_inv[n];
    float v0 = mus[(k0 + 0) * KPROTO + n] * inv;
    float v1 = mus[(k0 + 1) * KPROTO + n] * inv;
    float v2 = mus[(k0 + 8) * KPROTO + n] * inv;
    float v3 = mus[(k0 + 9) * KPROTO + n] * inv;
    float h0, l0, h1, l1, h2, l2, h3, l3;
    splith(v0, h0, l0); splith(v1, h1, l1);
    splith(v2, h2, l2); splith(v3, h3, l3);
    uint4 o;
    o.x = pack_h2(h0, h1);   // b0 hi
    o.y = pack_h2(h2, h3);   // b1 hi
    o.z = pack_h2(l0, l1);   // b0 lo
    o.w = pack_h2(l2, l3);   // b1 lo
    g_B[f * 32 + lane] = o;
}

// ---------------- prep 3: A fragments (fp16 hi only) ----------------
__global__ void prepA(const float* __restrict__ xs) {
    int tid  = threadIdx.x;
    int w    = tid >> 5;            // = ks
    int lane = tid & 31;
    int mb   = blockIdx.x;          // 0..4095
    int g    = lane >> 2;
    int t4   = lane & 3;
    int ks   = w;
    int r0 = mb * 16 + g;
    int r1 = r0 + 8;
    int c0 = ks * 16 + 2 * t4;
    float2 p00 = *(const float2*)&xs[(size_t)r0 * DDIM + c0];
    float2 p01 = *(const float2*)&xs[(size_t)r0 * DDIM + c0 + 8];
    float2 p10 = *(const float2*)&xs[(size_t)r1 * DDIM + c0];
    float2 p11 = *(const float2*)&xs[(size_t)r1 * DDIM + c0 + 8];
    uint4 oh;
    oh.x = pack_h2(p00.x, p00.y);
    oh.y = pack_h2(p10.x, p10.y);
    oh.z = pack_h2(p01.x, p01.y);
    oh.w = pack_h2(p11.x, p11.y);
    g_Ah[((size_t)mb * 8 + ks) * 32 + lane] = oh;
}

// ---------------- main: mma + fused softmin epilogue ----------------
// Block = 64 threads = 2 warps = 2 strips of 16 rows. No smem, no block sync.
// All warps sweep nb in the same order -> coherent B stream, L1 temporal reuse.
__global__ __launch_bounds__(THREADS, 12)
void main_kernel(float* __restrict__ out) {
    const int tid  = threadIdx.x;
    const int wid  = tid >> 5;
    const int lane = tid & 31;
    const int g    = lane >> 2;
    const int t4   = lane & 3;
    const int mb   = blockIdx.x * 2 + wid;

    // A fragments: fp16 hi, register-resident (8 ksteps x 4 regs)
    uint4 Ah[8];
    {
        const uint4* pA = g_Ah + (size_t)mb * 256 + lane;
#pragma unroll
        for (int ks = 0; ks < 8; ks++) Ah[ks] = pA[ks * 32];
    }

    float s0 = 0.0f, s1 = 0.0f;
    const float2* la_p = (const float2*)g_la;

#pragma unroll 1
    for (int nb = 0; nb < 128; nb++) {
        const uint4* pB = g_B + nb * 256 + lane;
        float2 la = la_p[nb * 4 + t4];
        ull la2 = pack2(la.x, la.y);

        float hh0 = 0, hh1 = 0, hh2 = 0, hh3 = 0;
        float hl0 = 0, hl1 = 0, hl2 = 0, hl3 = 0;
#pragma unroll
        for (int ks = 0; ks < 8; ks++) {
            uint4 b = pB[ks * 32];
            mma16816h(hh0, hh1, hh2, hh3, Ah[ks].x, Ah[ks].y, Ah[ks].z, Ah[ks].w, b.x, b.y);
            mma16816h(hl0, hl1, hl2, hl3, Ah[ks].x, Ah[ks].y, Ah[ks].z, Ah[ks].w, b.z, b.w);
        }
        float ip0 = hh0 + hl0;   // (row g,   col 2t4)
        float ip1 = hh1 + hl1;   // (row g,   col 2t4+1)
        float ip2 = hh2 + hl2;   // (row g+8, col 2t4)
        float ip3 = hh3 + hl3;   // (row g+8, col 2t4+1)
        float e0, e1, e2, e3;
        term2(ip0, ip1, la2, e0, e1);
        term2(ip2, ip3, la2, e2, e3);
        s0 += e0 + e1;
        s1 += e2 + e3;
    }

    // reduce across the 4 lanes sharing the same rows (t4 = 0..3)
    s0 += __shfl_xor_sync(0xffffffffu, s0, 1);
    s0 += __shfl_xor_sync(0xffffffffu, s0, 2);
    s1 += __shfl_xor_sync(0xffffffffu, s1, 1);
    s1 += __shfl_xor_sync(0xffffffffu, s1, 2);

    if (t4 == 0) {
        int r = mb * 16 + g;
        out[r]     = 0.1f * log1pf(1.0f / s0);
        out[r + 8] = 0.1f * log1pf(1.0f / s1);
    }
}

// ---------------- launch ----------------
extern "C" void kernel_launch(void* const* d_in, const int* in_sizes, int n_in,
                              void* d_out, int out_size) {
    const float* xs     = (const float*)d_in[0];
    const float* mus    = (const float*)d_in[1];
    const float* alphas = (const float*)d_in[2];
    float* out = (float*)d_out;

    int B = in_sizes[0] / DDIM;    // 65536

    prep1<<<(KPROTO + 255) / 256, 256>>>(mus, alphas);
    prep2<<<128, 256>>>(mus);
    prepA<<<B / 16, 256>>>(xs);
    main_kernel<<<B / 32, THREADS>>>(out);
}

// round 7
// speedup vs baseline: 8.7864x; 1.1907x over previous
#include <cuda_runtime.h>
#include <cuda_fp16.h>
#include <cstdint>

#define DDIM   128
#define KPROTO 1024
#define NMB    4096          // 65536/16 row-strips
#define THREADS 64
typedef unsigned int u32;
typedef unsigned long long ull;

// Fragment-layout operand storage (static device arrays; no allocation).
__device__ uint4 g_Ah[NMB * 8 * 32];    // A fp16 frags [mb][ks][lane] = {a0,a1,a2,a3}
__device__ uint4 g_B [128 * 8 * 32];    // 512 KB: B frags [nblock][ks][lane] = {b0h,b1h,b0l,b1l}
__device__ float g_la [KPROTO];         // -10*log2(e)*alpha
__device__ float g_inv[KPROTO];         // 1/||mu_col||

// ---------------- helpers ----------------
__device__ __forceinline__ u32 pack_h2(float a, float b) {
    __half2 t;
    t.x = __float2half_rn(a);
    t.y = __float2half_rn(b);
    return *reinterpret_cast<u32*>(&t);
}
__device__ __forceinline__ void splith(float v, float& h, float& l) {
    __half hh = __float2half_rn(v);
    h = __half2float(hh);
    l = v - h;
}
__device__ __forceinline__ ull pack2(float lo, float hi) {
    ull r; asm("mov.b64 %0, {%1, %2};" : "=l"(r) : "f"(lo), "f"(hi)); return r;
}
__device__ __forceinline__ void unpack2(ull v, float& lo, float& hi) {
    asm("mov.b64 {%0, %1}, %2;" : "=f"(lo), "=f"(hi) : "l"(v));
}
__device__ __forceinline__ ull fma2(ull a, ull b, ull c) {
    ull d; asm("fma.rn.f32x2 %0, %1, %2, %3;" : "=l"(d) : "l"(a), "l"(b), "l"(c)); return d;
}
__device__ __forceinline__ ull mul2(ull a, ull b) {
    ull d; asm("mul.rn.f32x2 %0, %1, %2;" : "=l"(d) : "l"(a), "l"(b)); return d;
}
__device__ __forceinline__ float ex2(float x) {
    float r; asm("ex2.approx.f32 %0, %1;" : "=f"(r) : "f"(x)); return r;
}
__device__ __forceinline__ float sqap(float x) {
    float r; asm("sqrt.approx.f32 %0, %1;" : "=f"(r) : "f"(x)); return r;
}
__device__ __forceinline__ void mma16816h(float& d0, float& d1, float& d2, float& d3,
                                          u32 a0, u32 a1, u32 a2, u32 a3,
                                          u32 b0, u32 b1) {
    asm volatile(
        "mma.sync.aligned.m16n8k16.row.col.f32.f16.f16.f32 "
        "{%0,%1,%2,%3},{%4,%5,%6,%7},{%8,%9},{%0,%1,%2,%3};"
        : "+f"(d0), "+f"(d1), "+f"(d2), "+f"(d3)
        : "r"(a0), "r"(a1), "r"(a2), "r"(a3), "r"(b0), "r"(b1));
}

// packed epilogue: e_i = exp2(-5*log2e*acos(ip_i)^2 + la_i) for a pair
__device__ __forceinline__ void term2(float ip0, float ip1, ull la2, float& e0, float& e1) {
    const float PI = 3.14159265358979f;
    float ax0 = fabsf(ip0), ax1 = fabsf(ip1);
    float sq0 = sqap(fmaxf(1.0f - ax0, 0.0f));
    float sq1 = sqap(fmaxf(1.0f - ax1, 0.0f));
    ull ax2 = pack2(ax0, ax1);
    // A&S 4.4.45 deg-7 Horner, packed
    ull P = pack2(-0.0012624911f, -0.0012624911f);
    P = fma2(P, ax2, pack2( 0.0066700901f,  0.0066700901f));
    P = fma2(P, ax2, pack2(-0.0170881256f, -0.0170881256f));
    P = fma2(P, ax2, pack2( 0.0308918810f,  0.0308918810f));
    P = fma2(P, ax2, pack2(-0.0501743046f, -0.0501743046f));
    P = fma2(P, ax2, pack2( 0.0889789874f,  0.0889789874f));
    P = fma2(P, ax2, pack2(-0.2145988016f, -0.2145988016f));
    P = fma2(P, ax2, pack2( 1.5707963050f,  1.5707963050f));
    float p0, p1; unpack2(P, p0, p1);
    float th0 = sq0 * p0;  th0 = (ip0 >= 0.0f) ? th0 : PI - th0;
    float th1 = sq1 * p1;  th1 = (ip1 >= 0.0f) ? th1 : PI - th1;
    ull th2 = pack2(th0, th1);
    ull z2  = fma2(mul2(th2, th2), pack2(-7.213475204444817f, -7.213475204444817f), la2);
    float z0, z1; unpack2(z2, z0, z1);
    e0 = ex2(z0);
    e1 = ex2(z1);
}

// ---------------- prep 1: column norms + log2-alpha ----------------
__global__ void prep1(const float* __restrict__ mus, const float* __restrict__ alphas) {
    int n = blockIdx.x * blockDim.x + threadIdx.x;
    if (n >= KPROTO) return;
    float s = 0.0f;
#pragma unroll 8
    for (int d = 0; d < DDIM; d++) {
        float v = mus[d * KPROTO + n];
        s = fmaf(v, v, s);
    }
    g_inv[n] = rsqrtf(s);
    g_la[n]  = -14.426950408889634f * alphas[n];   // -10*log2(e)*alpha
}

// ---------------- prep 2: B fragments (fp16 hi/lo) ----------------
__global__ void prep2(const float* __restrict__ mus) {
    int gid  = blockIdx.x * blockDim.x + threadIdx.x;   // 32768 threads
    int lane = gid & 31;
    int f    = gid >> 5;            // 0..1023 = nblock*8 + ks
    int nblk = f >> 3;
    int ks   = f & 7;
    int g    = lane >> 2;
    int t4   = lane & 3;
    int n    = nblk * 8 + g;
    int k0   = ks * 16 + 2 * t4;
    float inv = g_inv[n];
    float v0 = mus[(k0 + 0) * KPROTO + n] * inv;
    float v1 = mus[(k0 + 1) * KPROTO + n] * inv;
    float v2 = mus[(k0 + 8) * KPROTO + n] * inv;
    float v3 = mus[(k0 + 9) * KPROTO + n] * inv;
    float h0, l0, h1, l1, h2, l2, h3, l3;
    splith(v0, h0, l0); splith(v1, h1, l1);
    splith(v2, h2, l2); splith(v3, h3, l3);
    uint4 o;
    o.x = pack_h2(h0, h1);   // b0 hi
    o.y = pack_h2(h2, h3);   // b1 hi
    o.z = pack_h2(l0, l1);   // b0 lo
    o.w = pack_h2(l2, l3);   // b1 lo
    g_B[f * 32 + lane] = o;
}

// ---------------- prep 3: A fragments (fp16 hi only) ----------------
__global__ void prepA(const float* __restrict__ xs) {
    int tid  = threadIdx.x;
    int w    = tid >> 5;            // = ks
    int lane = tid & 31;
    int mb   = blockIdx.x;          // 0..4095
    int g    = lane >> 2;
    int t4   = lane & 3;
    int ks   = w;
    int r0 = mb * 16 + g;
    int r1 = r0 + 8;
    int c0 = ks * 16 + 2 * t4;
    float2 p00 = *(const float2*)&xs[(size_t)r0 * DDIM + c0];
    float2 p01 = *(const float2*)&xs[(size_t)r0 * DDIM + c0 + 8];
    float2 p10 = *(const float2*)&xs[(size_t)r1 * DDIM + c0];
    float2 p11 = *(const float2*)&xs[(size_t)r1 * DDIM + c0 + 8];
    uint4 oh;
    oh.x = pack_h2(p00.x, p00.y);
    oh.y = pack_h2(p10.x, p10.y);
    oh.z = pack_h2(p01.x, p01.y);
    oh.w = pack_h2(p11.x, p11.y);
    g_Ah[((size_t)mb * 8 + ks) * 32 + lane] = oh;
}

// ---------------- main: mma + fused softmin epilogue ----------------
// Block = 64 threads = 2 warps; each warp owns 2 row-strips (32 rows).
// 4 independent 8-deep MMA chains per iteration + software-pipelined epilogue
// (previous iteration's transcendental work interleaves with current MMAs).
__global__ __launch_bounds__(THREADS, 8)
void main_kernel(float* __restrict__ out) {
    const int tid  = threadIdx.x;
    const int wid  = tid >> 5;
    const int lane = tid & 31;
    const int g    = lane >> 2;
    const int t4   = lane & 3;
    const int mb0  = blockIdx.x * 4 + wid * 2;   // first strip; second is mb0+1

    // A fragments for both strips: register-resident (2 x 8 ksteps x 4 regs)
    uint4 A0[8], A1[8];
    {
        const uint4* p0 = g_Ah + (size_t)mb0 * 256 + lane;
#pragma unroll
        for (int ks = 0; ks < 8; ks++) { A0[ks] = p0[ks * 32]; A1[ks] = p0[256 + ks * 32]; }
    }

    float s0 = 0.0f, s1 = 0.0f, s2 = 0.0f, s3 = 0.0f;
    const float2* la_p = (const float2*)g_la;

    float ipp[8];        // previous iteration's inner products
    ull   lap = 0;       // previous iteration's packed la

    auto do_epi = [&]() {
        float e0, e1, e2, e3;
        term2(ipp[0], ipp[1], lap, e0, e1);
        term2(ipp[2], ipp[3], lap, e2, e3);
        s0 += e0 + e1;
        s1 += e2 + e3;
        term2(ipp[4], ipp[5], lap, e0, e1);
        term2(ipp[6], ipp[7], lap, e2, e3);
        s2 += e0 + e1;
        s3 += e2 + e3;
    };

#pragma unroll 1
    for (int nb = 0; nb < 128; nb++) {
        const uint4* pB = g_B + nb * 256 + lane;
        float2 la = la_p[nb * 4 + t4];

        float p0h0=0,p0h1=0,p0h2=0,p0h3=0;   // strip0 x B-hi
        float p0l0=0,p0l1=0,p0l2=0,p0l3=0;   // strip0 x B-lo
        float p1h0=0,p1h1=0,p1h2=0,p1h3=0;   // strip1 x B-hi
        float p1l0=0,p1l1=0,p1l2=0,p1l3=0;   // strip1 x B-lo

        // first half of K (ks 0..3)
        {
            uint4 b0 = pB[0], b1 = pB[32], b2 = pB[64], b3 = pB[96];
            mma16816h(p0h0,p0h1,p0h2,p0h3, A0[0].x,A0[0].y,A0[0].z,A0[0].w, b0.x,b0.y);
            mma16816h(p1h0,p1h1,p1h2,p1h3, A1[0].x,A1[0].y,A1[0].z,A1[0].w, b0.x,b0.y);
            mma16816h(p0l0,p0l1,p0l2,p0l3, A0[0].x,A0[0].y,A0[0].z,A0[0].w, b0.z,b0.w);
            mma16816h(p1l0,p1l1,p1l2,p1l3, A1[0].x,A1[0].y,A1[0].z,A1[0].w, b0.z,b0.w);
            mma16816h(p0h0,p0h1,p0h2,p0h3, A0[1].x,A0[1].y,A0[1].z,A0[1].w, b1.x,b1.y);
            mma16816h(p1h0,p1h1,p1h2,p1h3, A1[1].x,A1[1].y,A1[1].z,A1[1].w, b1.x,b1.y);
            mma16816h(p0l0,p0l1,p0l2,p0l3, A0[1].x,A0[1].y,A0[1].z,A0[1].w, b1.z,b1.w);
            mma16816h(p1l0,p1l1,p1l2,p1l3, A1[1].x,A1[1].y,A1[1].z,A1[1].w, b1.z,b1.w);
            mma16816h(p0h0,p0h1,p0h2,p0h3, A0[2].x,A0[2].y,A0[2].z,A0[2].w, b2.x,b2.y);
            mma16816h(p1h0,p1h1,p1h2,p1h3, A1[2].x,A1[2].y,A1[2].z,A1[2].w, b2.x,b2.y);
            mma16816h(p0l0,p0l1,p0l2,p0l3, A0[2].x,A0[2].y,A0[2].z,A0[2].w, b2.z,b2.w);
            mma16816h(p1l0,p1l1,p1l2,p1l3, A1[2].x,A1[2].y,A1[2].z,A1[2].w, b2.z,b2.w);
            mma16816h(p0h0,p0h1,p0h2,p0h3, A0[3].x,A0[3].y,A0[3].z,A0[3].w, b3.x,b3.y);
            mma16816h(p1h0,p1h1,p1h2,p1h3, A1[3].x,A1[3].y,A1[3].z,A1[3].w, b3.x,b3.y);
            mma16816h(p0l0,p0l1,p0l2,p0l3, A0[3].x,A0[3].y,A0[3].z,A0[3].w, b3.z,b3.w);
            mma16816h(p1l0,p1l1,p1l2,p1l3, A1[3].x,A1[3].y,A1[3].z,A1[3].w, b3.z,b3.w);
        }

        // epilogue of previous iteration overlaps current MMA chains
        if (nb > 0) do_epi();

        // second half of K (ks 4..7)
        {
            uint4 b4 = pB[128], b5 = pB[160], b6 = pB[192], b7 = pB[224];
            mma16816h(p0h0,p0h1,p0h2,p0h3, A0[4].x,A0[4].y,A0[4].z,A0[4].w, b4.x,b4.y);
            mma16816h(p1h0,p1h1,p1h2,p1h3, A1[4].x,A1[4].y,A1[4].z,A1[4].w, b4.x,b4.y);
            mma16816h(p0l0,p0l1,p0l2,p0l3, A0[4].x,A0[4].y,A0[4].z,A0[4].w, b4.z,b4.w);
            mma16816h(p1l0,p1l1,p1l2,p1l3, A1[4].x,A1[4].y,A1[4].z,A1[4].w, b4.z,b4.w);
            mma16816h(p0h0,p0h1,p0h2,p0h3, A0[5].x,A0[5].y,A0[5].z,A0[5].w, b5.x,b5.y);
            mma16816h(p1h0,p1h1,p1h2,p1h3, A1[5].x,A1[5].y,A1[5].z,A1[5].w, b5.x,b5.y);
            mma16816h(p0l0,p0l1,p0l2,p0l3, A0[5].x,A0[5].y,A0[5].z,A0[5].w, b5.z,b5.w);
            mma16816h(p1l0,p1l1,p1l2,p1l3, A1[5].x,A1[5].y,A1[5].z,A1[5].w, b5.z,b5.w);
            mma16816h(p0h0,p0h1,p0h2,p0h3, A0[6].x,A0[6].y,A0[6].z,A0[6].w, b6.x,b6.y);
            mma16816h(p1h0,p1h1,p1h2,p1h3, A1[6].x,A1[6].y,A1[6].z,A1[6].w, b6.x,b6.y);
            mma16816h(p0l0,p0l1,p0l2,p0l3, A0[6].x,A0[6].y,A0[6].z,A0[6].w, b6.z,b6.w);
            mma16816h(p1l0,p1l1,p1l2,p1l3, A1[6].x,A1[6].y,A1[6].z,A1[6].w, b6.z,b6.w);
            mma16816h(p0h0,p0h1,p0h2,p0h3, A0[7].x,A0[7].y,A0[7].z,A0[7].w, b7.x,b7.y);
            mma16816h(p1h0,p1h1,p1h2,p1h3, A1[7].x,A1[7].y,A1[7].z,A1[7].w, b7.x,b7.y);
            mma16816h(p0l0,p0l1,p0l2,p0l3, A0[7].x,A0[7].y,A0[7].z,A0[7].w, b7.z,b7.w);
            mma16816h(p1l0,p1l1,p1l2,p1l3, A1[7].x,A1[7].y,A1[7].z,A1[7].w, b7.z,b7.w);
        }

        ipp[0] = p0h0 + p0l0;  ipp[1] = p0h1 + p0l1;
        ipp[2] = p0h2 + p0l2;  ipp[3] = p0h3 + p0l3;
        ipp[4] = p1h0 + p1l0;  ipp[5] = p1h1 + p1l1;
        ipp[6] = p1h2 + p1l2;  ipp[7] = p1h3 + p1l3;
        lap = pack2(la.x, la.y);
    }
    do_epi();   // drain the pipeline

    // reduce across the 4 lanes sharing the same rows (t4 = 0..3)
    s0 += __shfl_xor_sync(0xffffffffu, s0, 1);
    s0 += __shfl_xor_sync(0xffffffffu, s0, 2);
    s1 += __shfl_xor_sync(0xffffffffu, s1, 1);
    s1 += __shfl_xor_sync(0xffffffffu, s1, 2);
    s2 += __shfl_xor_sync(0xffffffffu, s2, 1);
    s2 += __shfl_xor_sync(0xffffffffu, s2, 2);
    s3 += __shfl_xor_sync(0xffffffffu, s3, 1);
    s3 += __shfl_xor_sync(0xffffffffu, s3, 2);

    if (t4 == 0) {
        int r0 = mb0 * 16 + g;
        out[r0]      = 0.1f * log1pf(1.0f / s0);
        out[r0 + 8]  = 0.1f * log1pf(1.0f / s1);
        out[r0 + 16] = 0.1f * log1pf(1.0f / s2);
        out[r0 + 24] = 0.1f * log1pf(1.0f / s3);
    }
}

// ---------------- launch ----------------
extern "C" void kernel_launch(void* const* d_in, const int* in_sizes, int n_in,
                              void* d_out, int out_size) {
    const float* xs     = (const float*)d_in[0];
    const float* mus    = (const float*)d_in[1];
    const float* alphas = (const float*)d_in[2];
    float* out = (float*)d_out;

    int B = in_sizes[0] / DDIM;    // 65536

    prep1<<<(KPROTO + 255) / 256, 256>>>(mus, alphas);
    prep2<<<128, 256>>>(mus);
    prepA<<<B / 16, 256>>>(xs);
    main_kernel<<<B / 64, THREADS>>>(out);
}

// round 8
// speedup vs baseline: 14.9358x; 1.6999x over previous
#include <cuda_runtime.h>
#include <cuda_fp16.h>
#include <cstdint>

#define DDIM   128
#define KPROTO 1024
#define NMB    4096          // 65536/16 row-strips
#define THREADS 64
typedef unsigned int u32;
typedef unsigned long long ull;

// Fragment-layout operand storage (static device arrays; no allocation).
__device__ uint4 g_Ah[NMB * 8 * 32];    // A fp16 frags [mb][ks][lane] = {a0,a1,a2,a3}
__device__ uint4 g_B [64 * 8 * 32];     // 256 KB: B-hi frags [nbpair][ks][lane] = {b0E,b1E,b0O,b1O}
__device__ float g_la [KPROTO];         // -10*log2e*alpha - c*pi^2/4
__device__ float g_inv[KPROTO];         // 1/||mu_col||

// ---------------- helpers ----------------
__device__ __forceinline__ u32 pack_h2(float a, float b) {
    __half2 t;
    t.x = __float2half_rn(a);
    t.y = __float2half_rn(b);
    return *reinterpret_cast<u32*>(&t);
}
__device__ __forceinline__ ull pack2(float lo, float hi) {
    ull r; asm("mov.b64 %0, {%1, %2};" : "=l"(r) : "f"(lo), "f"(hi)); return r;
}
__device__ __forceinline__ void unpack2(ull v, float& lo, float& hi) {
    asm("mov.b64 {%0, %1}, %2;" : "=f"(lo), "=f"(hi) : "l"(v));
}
__device__ __forceinline__ ull fma2(ull a, ull b, ull c) {
    ull d; asm("fma.rn.f32x2 %0, %1, %2, %3;" : "=l"(d) : "l"(a), "l"(b), "l"(c)); return d;
}
__device__ __forceinline__ ull mul2(ull a, ull b) {
    ull d; asm("mul.rn.f32x2 %0, %1, %2;" : "=l"(d) : "l"(a), "l"(b)); return d;
}
__device__ __forceinline__ float ex2(float x) {
    float r; asm("ex2.approx.f32 %0, %1;" : "=f"(r) : "f"(x)); return r;
}
__device__ __forceinline__ void mma16816h(float& d0, float& d1, float& d2, float& d3,
                                          u32 a0, u32 a1, u32 a2, u32 a3,
                                          u32 b0, u32 b1) {
    asm volatile(
        "mma.sync.aligned.m16n8k16.row.col.f32.f16.f16.f32 "
        "{%0,%1,%2,%3},{%4,%5,%6,%7},{%8,%9},{%0,%1,%2,%3};"
        : "+f"(d0), "+f"(d1), "+f"(d2), "+f"(d3)
        : "r"(a0), "r"(a1), "r"(a2), "r"(a3), "r"(b0), "r"(b1));
}

// ---------------- prep 1: column norms + folded alpha const ----------------
// exponent(p) = -c*p^2 + c*pi*p + (la), with la = -10*log2e*alpha - c*pi^2/4,
// where p = asin(ip), c = 5*log2(e).
__global__ void prep1(const float* __restrict__ mus, const float* __restrict__ alphas) {
    int n = blockIdx.x * blockDim.x + threadIdx.x;
    if (n >= KPROTO) return;
    float s = 0.0f;
#pragma unroll 8
    for (int d = 0; d < DDIM; d++) {
        float v = mus[d * KPROTO + n];
        s = fmaf(v, v, s);
    }
    g_inv[n] = rsqrtf(s);
    g_la[n]  = fmaf(-14.4269504088896340f, alphas[n], -17.7985387f);
}

// ---------------- prep 2: B-hi fragments, packed per nb-pair ----------------
__global__ void prep2(const float* __restrict__ mus) {
    int gid  = blockIdx.x * blockDim.x + threadIdx.x;   // 16384 threads
    int lane = gid & 31;
    int f    = gid >> 5;            // 0..511 = nbpair*8 + ks
    int np   = f >> 3;              // nb pair index (covers nb=2np, 2np+1)
    int ks   = f & 7;
    int g    = lane >> 2;
    int t4   = lane & 3;
    int k0   = ks * 16 + 2 * t4;
    int nE   = (2 * np) * 8 + g;
    int nO   = nE + 8;
    float iE = g_inv[nE], iO = g_inv[nO];
    float e0 = mus[(k0 + 0) * KPROTO + nE] * iE;
    float e1 = mus[(k0 + 1) * KPROTO + nE] * iE;
    float e2 = mus[(k0 + 8) * KPROTO + nE] * iE;
    float e3 = mus[(k0 + 9) * KPROTO + nE] * iE;
    float o0 = mus[(k0 + 0) * KPROTO + nO] * iO;
    float o1 = mus[(k0 + 1) * KPROTO + nO] * iO;
    float o2 = mus[(k0 + 8) * KPROTO + nO] * iO;
    float o3 = mus[(k0 + 9) * KPROTO + nO] * iO;
    uint4 o;
    o.x = pack_h2(e0, e1);   // nbE b0
    o.y = pack_h2(e2, e3);   // nbE b1
    o.z = pack_h2(o0, o1);   // nbO b0
    o.w = pack_h2(o2, o3);   // nbO b1
    g_B[f * 32 + lane] = o;
}

// ---------------- prep 3: A fragments (fp16 hi) ----------------
__global__ void prepA(const float* __restrict__ xs) {
    int tid  = threadIdx.x;
    int ks   = tid >> 5;
    int lane = tid & 31;
    int mb   = blockIdx.x;          // 0..4095
    int g    = lane >> 2;
    int t4   = lane & 3;
    int r0 = mb * 16 + g;
    int r1 = r0 + 8;
    int c0 = ks * 16 + 2 * t4;
    float2 p00 = *(const float2*)&xs[(size_t)r0 * DDIM + c0];
    float2 p01 = *(const float2*)&xs[(size_t)r0 * DDIM + c0 + 8];
    float2 p10 = *(const float2*)&xs[(size_t)r1 * DDIM + c0];
    float2 p11 = *(const float2*)&xs[(size_t)r1 * DDIM + c0 + 8];
    uint4 oh;
    oh.x = pack_h2(p00.x, p00.y);
    oh.y = pack_h2(p10.x, p10.y);
    oh.z = pack_h2(p01.x, p01.y);
    oh.w = pack_h2(p11.x, p11.y);
    g_Ah[((size_t)mb * 8 + ks) * 32 + lane] = oh;
}

// ---------------- main: single-product mma + asin-based epilogue ----------------
// Block = 64 threads = 2 warps; warp owns 2 strips (32 rows), iterates 64 nb-pairs.
// 4 independent 8-deep MMA chains/iter; prev-iter epilogue interleaved in halves.
__global__ __launch_bounds__(THREADS, 7)
void main_kernel(float* __restrict__ out) {
    const int tid  = threadIdx.x;
    const int wid  = tid >> 5;
    const int lane = tid & 31;
    const int g    = lane >> 2;
    const int t4   = lane & 3;
    const int mb0  = blockIdx.x * 4 + wid * 2;   // first strip; second is mb0+1

    // A fragments for both strips: register-resident
    uint4 A0[8], A1[8];
    {
        const uint4* p0 = g_Ah + (size_t)mb0 * 256 + lane;
#pragma unroll
        for (int ks = 0; ks < 8; ks++) { A0[ks] = p0[ks * 32]; A1[ks] = p0[256 + ks * 32]; }
    }

    // asin Taylor (odd, deg 11) + exponent-fold constants
    const ull CA1 = pack2(0.16666667f,  0.16666667f);
    const ull CA2 = pack2(0.075f,       0.075f);
    const ull CA3 = pack2(0.044642857f, 0.044642857f);
    const ull CA4 = pack2(0.030381944f, 0.030381944f);
    const ull CA5 = pack2(0.022372159f, 0.022372159f);
    const ull NEGC = pack2(-7.2134752f, -7.2134752f);
    const ull CPI  = pack2(22.6618023f, 22.6618023f);

    // e(x0)+e(x1) for one packed pair with packed la
    auto tpair = [&](ull x2, ull la2) -> float {
        ull u  = mul2(x2, x2);
        ull q  = fma2(CA5, u, CA4);
        q = fma2(q, u, CA3);
        q = fma2(q, u, CA2);
        q = fma2(q, u, CA1);
        ull xu = mul2(x2, u);
        ull p  = fma2(xu, q, x2);     // asin(x)
        ull t  = fma2(p, NEGC, CPI);
        ull z  = fma2(p, t, la2);     // -c*p^2 + c*pi*p + la'
        float z0, z1; unpack2(z, z0, z1);
        return ex2(z0) + ex2(z1);
    };

    float s0 = 0.0f, s1 = 0.0f, s2 = 0.0f, s3 = 0.0f;
    const float2* la_p = (const float2*)g_la;

    ull ipp[8];            // prev iter packed ips: [E s0 g, E s0 g8, O s0 g, O s0 g8, E s1 g, ...]
    ull lapE = 0, lapO = 0;

#pragma unroll 1
    for (int it = 0; it < 64; it++) {
        const uint4* pB = g_B + it * 256 + lane;
        float2 laEf = la_p[(2 * it) * 4 + t4];
        float2 laOf = la_p[(2 * it + 1) * 4 + t4];

        float E00=0,E01=0,E02=0,E03=0;   // strip0 x nbE
        float E10=0,E11=0,E12=0,E13=0;   // strip1 x nbE
        float O00=0,O01=0,O02=0,O03=0;   // strip0 x nbO
        float O10=0,O11=0,O12=0,O13=0;   // strip1 x nbO

        // ks 0..3
        {
            uint4 b0 = pB[0], b1 = pB[32], b2 = pB[64], b3 = pB[96];
            mma16816h(E00,E01,E02,E03, A0[0].x,A0[0].y,A0[0].z,A0[0].w, b0.x,b0.y);
            mma16816h(E10,E11,E12,E13, A1[0].x,A1[0].y,A1[0].z,A1[0].w, b0.x,b0.y);
            mma16816h(O00,O01,O02,O03, A0[0].x,A0[0].y,A0[0].z,A0[0].w, b0.z,b0.w);
            mma16816h(O10,O11,O12,O13, A1[0].x,A1[0].y,A1[0].z,A1[0].w, b0.z,b0.w);
            mma16816h(E00,E01,E02,E03, A0[1].x,A0[1].y,A0[1].z,A0[1].w, b1.x,b1.y);
            mma16816h(E10,E11,E12,E13, A1[1].x,A1[1].y,A1[1].z,A1[1].w, b1.x,b1.y);
            mma16816h(O00,O01,O02,O03, A0[1].x,A0[1].y,A0[1].z,A0[1].w, b1.z,b1.w);
            mma16816h(O10,O11,O12,O13, A1[1].x,A1[1].y,A1[1].z,A1[1].w, b1.z,b1.w);
            mma16816h(E00,E01,E02,E03, A0[2].x,A0[2].y,A0[2].z,A0[2].w, b2.x,b2.y);
            mma16816h(E10,E11,E12,E13, A1[2].x,A1[2].y,A1[2].z,A1[2].w, b2.x,b2.y);
            mma16816h(O00,O01,O02,O03, A0[2].x,A0[2].y,A0[2].z,A0[2].w, b2.z,b2.w);
            mma16816h(O10,O11,O12,O13, A1[2].x,A1[2].y,A1[2].z,A1[2].w, b2.z,b2.w);
            mma16816h(E00,E01,E02,E03, A0[3].x,A0[3].y,A0[3].z,A0[3].w, b3.x,b3.y);
            mma16816h(E10,E11,E12,E13, A1[3].x,A1[3].y,A1[3].z,A1[3].w, b3.x,b3.y);
            mma16816h(O00,O01,O02,O03, A0[3].x,A0[3].y,A0[3].z,A0[3].w, b3.z,b3.w);
            mma16816h(O10,O11,O12,O13, A1[3].x,A1[3].y,A1[3].z,A1[3].w, b3.z,b3.w);
        }

        // prev-iter epilogue, strip0 (overlaps current MMA chains)
        if (it > 0) {
            s0 += tpair(ipp[0], lapE) + tpair(ipp[2], lapO);
            s1 += tpair(ipp[1], lapE) + tpair(ipp[3], lapO);
        }

        // ks 4..7
        {
            uint4 b4 = pB[128], b5 = pB[160], b6 = pB[192], b7 = pB[224];
            mma16816h(E00,E01,E02,E03, A0[4].x,A0[4].y,A0[4].z,A0[4].w, b4.x,b4.y);
            mma16816h(E10,E11,E12,E13, A1[4].x,A1[4].y,A1[4].z,A1[4].w, b4.x,b4.y);
            mma16816h(O00,O01,O02,O03, A0[4].x,A0[4].y,A0[4].z,A0[4].w, b4.z,b4.w);
            mma16816h(O10,O11,O12,O13, A1[4].x,A1[4].y,A1[4].z,A1[4].w, b4.z,b4.w);
            mma16816h(E00,E01,E02,E03, A0[5].x,A0[5].y,A0[5].z,A0[5].w, b5.x,b5.y);
            mma16816h(E10,E11,E12,E13, A1[5].x,A1[5].y,A1[5].z,A1[5].w, b5.x,b5.y);
            mma16816h(O00,O01,O02,O03, A0[5].x,A0[5].y,A0[5].z,A0[5].w, b5.z,b5.w);
            mma16816h(O10,O11,O12,O13, A1[5].x,A1[5].y,A1[5].z,A1[5].w, b5.z,b5.w);
            mma16816h(E00,E01,E02,E03, A0[6].x,A0[6].y,A0[6].z,A0[6].w, b6.x,b6.y);
            mma16816h(E10,E11,E12,E13, A1[6].x,A1[6].y,A1[6].z,A1[6].w, b6.x,b6.y);
            mma16816h(O00,O01,O02,O03, A0[6].x,A0[6].y,A0[6].z,A0[6].w, b6.z,b6.w);
            mma16816h(O10,O11,O12,O13, A1[6].x,A1[6].y,A1[6].z,A1[6].w, b6.z,b6.w);
            mma16816h(E00,E01,E02,E03, A0[7].x,A0[7].y,A0[7].z,A0[7].w, b7.x,b7.y);
            mma16816h(E10,E11,E12,E13, A1[7].x,A1[7].y,A1[7].z,A1[7].w, b7.x,b7.y);
            mma16816h(O00,O01,O02,O03, A0[7].x,A0[7].y,A0[7].z,A0[7].w, b7.z,b7.w);
            mma16816h(O10,O11,O12,O13, A1[7].x,A1[7].y,A1[7].z,A1[7].w, b7.z,b7.w);
        }

        // prev-iter epilogue, strip1
        if (it > 0) {
            s2 += tpair(ipp[4], lapE) + tpair(ipp[6], lapO);
            s3 += tpair(ipp[5], lapE) + tpair(ipp[7], lapO);
        }

        ipp[0] = pack2(E00, E01);  ipp[1] = pack2(E02, E03);
        ipp[2] = pack2(O00, O01);  ipp[3] = pack2(O02, O03);
        ipp[4] = pack2(E10, E11);  ipp[5] = pack2(E12, E13);
        ipp[6] = pack2(O10, O11);  ipp[7] = pack2(O12, O13);
        lapE = pack2(laEf.x, laEf.y);
        lapO = pack2(laOf.x, laOf.y);
    }

    // drain pipeline
    s0 += tpair(ipp[0], lapE) + tpair(ipp[2], lapO);
    s1 += tpair(ipp[1], lapE) + tpair(ipp[3], lapO);
    s2 += tpair(ipp[4], lapE) + tpair(ipp[6], lapO);
    s3 += tpair(ipp[5], lapE) + tpair(ipp[7], lapO);

    // reduce across the 4 lanes sharing the same rows (t4 = 0..3)
    s0 += __shfl_xor_sync(0xffffffffu, s0, 1);
    s0 += __shfl_xor_sync(0xffffffffu, s0, 2);
    s1 += __shfl_xor_sync(0xffffffffu, s1, 1);
    s1 += __shfl_xor_sync(0xffffffffu, s1, 2);
    s2 += __shfl_xor_sync(0xffffffffu, s2, 1);
    s2 += __shfl_xor_sync(0xffffffffu, s2, 2);
    s3 += __shfl_xor_sync(0xffffffffu, s3, 1);
    s3 += __shfl_xor_sync(0xffffffffu, s3, 2);

    if (t4 == 0) {
        int r0 = mb0 * 16 + g;
        out[r0]      = 0.1f * log1pf(1.0f / s0);
        out[r0 + 8]  = 0.1f * log1pf(1.0f / s1);
        out[r0 + 16] = 0.1f * log1pf(1.0f / s2);
        out[r0 + 24] = 0.1f * log1pf(1.0f / s3);
    }
}

// ---------------- launch ----------------
extern "C" void kernel_launch(void* const* d_in, const int* in_sizes, int n_in,
                              void* d_out, int out_size) {
    const float* xs     = (const float*)d_in[0];
    const float* mus    = (const float*)d_in[1];
    const float* alphas = (const float*)d_in[2];
    float* out = (float*)d_out;

    int B = in_sizes[0] / DDIM;    // 65536

    prep1<<<(KPROTO + 255) / 256, 256>>>(mus, alphas);
    prep2<<<64, 256>>>(mus);
    prepA<<<B / 16, 256>>>(xs);
    main_kernel<<<B / 64, THREADS>>>(out);
}